// round 1
// baseline (speedup 1.0000x reference)
#include <cuda_runtime.h>
#include <math.h>

// Problem constants
#define Bb   8
#define Cch  128
#define Lsp  4096            // 16*16*16
#define CL   (Cch*Lsp)       // 524288
#define C4L  (4*CL)

// ---------------- scratch (static device memory, no allocation) -------------
__device__ float g_y1[Bb*CL];          // dwblock stage 1 output
__device__ float g_y2[Bb*CL];          // dwblock depthwise output
__device__ float g_q [Bb*CL];          // query features
__device__ float g_K [Bb*C4L];         // concatenated keys   [B,4C,L]
__device__ float g_V [Bb*C4L];         // concatenated values [B,4C,L]
__device__ float g_x [Bb*CL];          // attention output
__device__ float g_at[Bb*128*512];     // attention scores [B,C,4C]

__device__ __forceinline__ float gelu_exact(float x) {
    return 0.5f * x * (1.0f + erff(x * 0.70710678118654752f));
}

// ---------------------------------------------------------------------------
// Fused pointwise-conv block:
//   optional:  input LN (over 128 channels per token) + GELU
//   GEMM:      out[o,t] = sum_c W[o,c] * x[c,t] + bias[o]
//   output LN  (over 128 channels per token)
//   optional:  output GELU
//   optional:  residual add
// Tile: 128 output channels x 32 tokens per block, 256 threads.
// flags: bit0 = input LN+GELU, bit1 = output GELU, bit2 = residual add
// ---------------------------------------------------------------------------
__global__ __launch_bounds__(256) void pw_fused(
    const float* __restrict__ in,  long in_bs,
    const float* __restrict__ W,   const float* __restrict__ bias,
    const float* __restrict__ gi,  const float* __restrict__ bi,
    const float* __restrict__ go,  const float* __restrict__ bo,
    const float* __restrict__ res, long res_bs,
    float*       __restrict__ out, long out_bs,
    int flags)
{
    __shared__ float xs[128 * 32];        // input tile [c][t]
    __shared__ float ws[32 * 129];        // W chunk [c_local][o], padded
    __shared__ float red[2][8][32];       // LN partials

    const int tid = threadIdx.x;
    const int tx  = tid & 31;             // token within tile
    const int ty  = tid >> 5;             // 8 channel groups
    const int b   = blockIdx.y;
    const int l0  = blockIdx.x * 32;

    const float* inb = in + (long)b * in_bs + l0;

    // load input tile (coalesced: 32 consecutive tokens per channel row)
    for (int idx = tid; idx < 4096; idx += 256)
        xs[idx] = inb[(long)(idx >> 5) * Lsp + (idx & 31)];
    __syncthreads();

    // ---- optional input LayerNorm + GELU (per token over 128 channels) ----
    if (flags & 1) {
        float v[16], s = 0.f, ss = 0.f;
#pragma unroll
        for (int k = 0; k < 16; k++) {
            float x = xs[(ty * 16 + k) * 32 + tx];
            v[k] = x; s += x; ss += x * x;
        }
        red[0][ty][tx] = s; red[1][ty][tx] = ss;
        __syncthreads();
        float S = 0.f, SS = 0.f;
#pragma unroll
        for (int j = 0; j < 8; j++) { S += red[0][j][tx]; SS += red[1][j][tx]; }
        float mean = S * (1.f / 128.f);
        float var  = SS * (1.f / 128.f) - mean * mean;
        float rstd = rsqrtf(var + 1e-6f);
#pragma unroll
        for (int k = 0; k < 16; k++) {
            int c = ty * 16 + k;
            float xh = (v[k] - mean) * rstd * gi[c] + bi[c];
            xs[c * 32 + tx] = gelu_exact(xh);
        }
        __syncthreads();
    }

    // ---- GEMM: each thread -> 16 output channels (o = ty*16+i), token tx ----
    float acc[16];
#pragma unroll
    for (int i = 0; i < 16; i++) acc[i] = bias[ty * 16 + i];

    for (int c0 = 0; c0 < 128; c0 += 32) {
        __syncthreads();
        for (int idx = tid; idx < 4096; idx += 256) {
            int o = idx >> 5, cl = idx & 31;
            ws[cl * 129 + o] = W[o * 128 + c0 + cl];
        }
        __syncthreads();
#pragma unroll 4
        for (int cl = 0; cl < 32; cl++) {
            float xv = xs[(c0 + cl) * 32 + tx];
#pragma unroll
            for (int i = 0; i < 16; i++)
                acc[i] += ws[cl * 129 + ty * 16 + i] * xv;
        }
    }

    // ---- output LayerNorm ----
    __syncthreads();
    {
        float s = 0.f, ss = 0.f;
#pragma unroll
        for (int i = 0; i < 16; i++) { s += acc[i]; ss += acc[i] * acc[i]; }
        red[0][ty][tx] = s; red[1][ty][tx] = ss;
    }
    __syncthreads();
    float S = 0.f, SS = 0.f;
#pragma unroll
    for (int j = 0; j < 8; j++) { S += red[0][j][tx]; SS += red[1][j][tx]; }
    float mean = S * (1.f / 128.f);
    float var  = SS * (1.f / 128.f) - mean * mean;
    float rstd = rsqrtf(var + 1e-6f);

    float* outb = out + (long)b * out_bs + l0;
    const float* resb = (flags & 4) ? (res + (long)b * res_bs + l0) : nullptr;
#pragma unroll
    for (int i = 0; i < 16; i++) {
        int o = ty * 16 + i;
        float v = (acc[i] - mean) * rstd * go[o] + bo[o];
        if (flags & 2) v = gelu_exact(v);
        if (flags & 4) v += resb[(long)o * Lsp + tx];
        outb[(long)o * Lsp + tx] = v;
    }
}

// ---------------------------------------------------------------------------
// Depthwise 3x3x3 conv, SAME zero padding, + bias.
// One block per (z-plane, channel, batch); 256 threads = 16x16 xy plane.
// ---------------------------------------------------------------------------
__global__ __launch_bounds__(256) void dw_conv(
    const float* __restrict__ in, const float* __restrict__ w27,
    const float* __restrict__ bias, float* __restrict__ out)
{
    __shared__ float sp[3][256];
    __shared__ float wsm[27];

    const int tid = threadIdx.x;
    const int x = tid & 15, y = tid >> 4;
    const int z = blockIdx.x;
    const int c = blockIdx.y;
    const int b = blockIdx.z;

    const long base = ((long)b * Cch + c) * Lsp;
#pragma unroll
    for (int p = 0; p < 3; p++) {
        int zz = z - 1 + p;
        sp[p][tid] = (zz >= 0 && zz < 16) ? in[base + zz * 256 + tid] : 0.f;
    }
    if (tid < 27) wsm[tid] = w27[c * 27 + tid];
    __syncthreads();

    float acc = bias[c];
#pragma unroll
    for (int dz = 0; dz < 3; dz++)
#pragma unroll
        for (int dy = 0; dy < 3; dy++)
#pragma unroll
            for (int dx = 0; dx < 3; dx++) {
                int yy = y + dy - 1, xx = x + dx - 1;
                if (yy >= 0 && yy < 16 && xx >= 0 && xx < 16)
                    acc += sp[dz][yy * 16 + xx] * wsm[dz * 9 + dy * 3 + dx];
            }
    out[base + z * 256 + tid] = acc;
}

// ---------------------------------------------------------------------------
// attn[b,c,k] = (1/64) * sum_l q[b,c,l] * K[b,k,l]
// ---------------------------------------------------------------------------
__global__ __launch_bounds__(256) void attn_qk(
    const float* __restrict__ q, const float* __restrict__ K,
    float* __restrict__ attn)
{
    __shared__ float qa[32 * 33];
    __shared__ float kb[32 * 33];
    const int tid = threadIdx.x;
    const int tx = tid & 31, ty = tid >> 5;
    const int k0 = blockIdx.x * 32;
    const int c0 = blockIdx.y * 32;
    const int b  = blockIdx.z;

    const float* qb = q + (long)b * CL  + (long)c0 * Lsp;
    const float* Kb = K + (long)b * C4L + (long)k0 * Lsp;

    float acc[4] = {0.f, 0.f, 0.f, 0.f};
    for (int l0 = 0; l0 < Lsp; l0 += 32) {
        for (int idx = tid; idx < 1024; idx += 256) {
            int r = idx >> 5, ll = idx & 31;
            qa[r * 33 + ll] = qb[(long)r * Lsp + l0 + ll];
            kb[r * 33 + ll] = Kb[(long)r * Lsp + l0 + ll];
        }
        __syncthreads();
#pragma unroll 8
        for (int ll = 0; ll < 32; ll++) {
            float kv = kb[tx * 33 + ll];
#pragma unroll
            for (int i = 0; i < 4; i++)
                acc[i] += qa[(ty * 4 + i) * 33 + ll] * kv;
        }
        __syncthreads();
    }
    float* ab = attn + (long)b * (128 * 512);
#pragma unroll
    for (int i = 0; i < 4; i++)
        ab[(long)(c0 + ty * 4 + i) * 512 + k0 + tx] = acc[i] * 0.015625f;
}

// ---------------------------------------------------------------------------
// Masked softmax over the 512 key positions of one (b,c) row.
// ---------------------------------------------------------------------------
__global__ __launch_bounds__(128) void softmax_mask(
    float* __restrict__ attn, const int* __restrict__ mask)
{
    __shared__ float sm[128];
    const int row = blockIdx.x;           // b*128 + c
    const int b = row >> 7;
    const int t = threadIdx.x;
    float* p = attn + (long)row * 512;

    float v[4];
    float mx = -INFINITY;
#pragma unroll
    for (int j = 0; j < 4; j++) {
        bool on = mask[b * 4 + j] > 0;
        v[j] = on ? p[j * 128 + t] : -INFINITY;
        mx = fmaxf(mx, v[j]);
    }
    sm[t] = mx; __syncthreads();
    for (int s = 64; s > 0; s >>= 1) {
        if (t < s) sm[t] = fmaxf(sm[t], sm[t + s]);
        __syncthreads();
    }
    mx = sm[0]; __syncthreads();

    float sum = 0.f;
#pragma unroll
    for (int j = 0; j < 4; j++) {
        v[j] = (v[j] == -INFINITY) ? 0.f : expf(v[j] - mx);
        sum += v[j];
    }
    sm[t] = sum; __syncthreads();
    for (int s = 64; s > 0; s >>= 1) {
        if (t < s) sm[t] += sm[t + s];
        __syncthreads();
    }
    float inv = 1.f / sm[0];
#pragma unroll
    for (int j = 0; j < 4; j++) p[j * 128 + t] = v[j] * inv;
}

// ---------------------------------------------------------------------------
// x[b,c,l] = sum_k attn[b,c,k] * V[b,k,l]
// ---------------------------------------------------------------------------
__global__ __launch_bounds__(256) void attn_v(
    const float* __restrict__ attn, const float* __restrict__ V,
    float* __restrict__ out)
{
    __shared__ float ac[32 * 33];
    __shared__ float vc[32 * 33];
    const int tid = threadIdx.x;
    const int tx = tid & 31, ty = tid >> 5;
    const int l0 = blockIdx.x * 32;
    const int c0 = blockIdx.y * 32;
    const int b  = blockIdx.z;

    const float* ab = attn + (long)b * (128 * 512) + (long)c0 * 512;
    const float* Vb = V + (long)b * C4L;

    float acc[4] = {0.f, 0.f, 0.f, 0.f};
    for (int k0 = 0; k0 < 512; k0 += 32) {
        for (int idx = tid; idx < 1024; idx += 256) {
            int r = idx >> 5, j = idx & 31;
            ac[r * 33 + j] = ab[(long)r * 512 + k0 + j];
            vc[r * 33 + j] = Vb[(long)(k0 + r) * Lsp + l0 + j];
        }
        __syncthreads();
#pragma unroll 8
        for (int kk = 0; kk < 32; kk++) {
            float vv = vc[kk * 33 + tx];
#pragma unroll
            for (int i = 0; i < 4; i++)
                acc[i] += ac[(ty * 4 + i) * 33 + kk] * vv;
        }
        __syncthreads();
    }
    float* ob = out + (long)b * CL + l0;
#pragma unroll
    for (int i = 0; i < 4; i++)
        ob[(long)(c0 + ty * 4 + i) * Lsp + tx] = acc[i];
}

// ---------------------------------------------------------------------------
// Host orchestration
// ---------------------------------------------------------------------------
extern "C" void kernel_launch(void* const* d_in, const int* in_sizes, int n_in,
                              void* d_out, int out_size)
{
    const float* query = (const float*)d_in[0];
    const float* mods[4] = { (const float*)d_in[1], (const float*)d_in[2],
                             (const float*)d_in[3], (const float*)d_in[4] };
    const int*   mask  = (const int*)d_in[5];
    const float* pw1_w = (const float*)d_in[6];
    const float* pw1_b = (const float*)d_in[7];
    const float* ln1_g = (const float*)d_in[8];
    const float* ln1_b = (const float*)d_in[9];
    const float* dw_w  = (const float*)d_in[10];
    const float* dw_b  = (const float*)d_in[11];
    const float* ln2_g = (const float*)d_in[12];
    const float* ln2_b = (const float*)d_in[13];
    const float* pw2_w = (const float*)d_in[14];
    const float* pw2_b = (const float*)d_in[15];
    const float* ln3_g = (const float*)d_in[16];
    const float* ln3_b = (const float*)d_in[17];
    float* out = (float*)d_out;

    float *y1, *y2, *qb, *Kb, *Vb, *xb, *at;
    cudaGetSymbolAddress((void**)&y1, g_y1);
    cudaGetSymbolAddress((void**)&y2, g_y2);
    cudaGetSymbolAddress((void**)&qb, g_q);
    cudaGetSymbolAddress((void**)&Kb, g_K);
    cudaGetSymbolAddress((void**)&Vb, g_V);
    cudaGetSymbolAddress((void**)&xb, g_x);
    cudaGetSymbolAddress((void**)&at, g_at);

    const dim3 pw_grid(Lsp / 32, Bb);
    const dim3 dw_grid(16, Cch, Bb);

    // one DepthWiseConvBlock = K1 (pw1+LN1+GELU) -> K2 (dw+bias) -> K3 (LN2+GELU+pw2+LN3[+res])
    auto run_block = [&](int i, const float* src, long src_bs,
                         float* dst, long dst_bs,
                         const float* res, long res_bs) {
        pw_fused<<<pw_grid, 256>>>(
            src, src_bs,
            pw1_w + (long)i * 128 * 128, pw1_b + i * 128,
            nullptr, nullptr,
            ln1_g + i * 128, ln1_b + i * 128,
            nullptr, 0,
            y1, CL,
            /*flags=*/2 /* out GELU */);
        dw_conv<<<dw_grid, 256>>>(
            y1, dw_w + (long)i * 128 * 27, dw_b + i * 128, y2);
        int flags = 1 /* in LN+GELU */ | (res ? 4 : 0);
        pw_fused<<<pw_grid, 256>>>(
            y2, CL,
            pw2_w + (long)i * 128 * 128, pw2_b + i * 128,
            ln2_g + i * 128, ln2_b + i * 128,
            ln3_g + i * 128, ln3_b + i * 128,
            res, res_bs,
            dst, dst_bs,
            flags);
    };

    // block 0: query map
    run_block(0, query, CL, qb, CL, nullptr, 0);
    // blocks 1-4: key maps -> write directly into concatenated K buffer
    for (int j = 0; j < 4; j++)
        run_block(1 + j, mods[j], CL, Kb + (long)j * CL, C4L, nullptr, 0);
    // blocks 5-8: value maps -> concatenated V buffer
    for (int j = 0; j < 4; j++)
        run_block(5 + j, mods[j], CL, Vb + (long)j * CL, C4L, nullptr, 0);

    // attention
    attn_qk<<<dim3(512 / 32, 128 / 32, Bb), 256>>>(qb, Kb, at);
    softmax_mask<<<Bb * 128, 128>>>(at, mask);
    attn_v<<<dim3(Lsp / 32, 128 / 32, Bb), 256>>>(at, Vb, xb);

    // block 9: out_project, residual = query, writes final output
    run_block(9, xb, CL, out, CL, query, CL);
}

// round 2
// speedup vs baseline: 1.8146x; 1.8146x over previous
#include <cuda_runtime.h>
#include <math.h>

#define Bb   8
#define Cch  128
#define Lsp  4096
#define CL   (Cch*Lsp)        // 524288
#define C4L  (4*CL)
#define BCL  (Bb*CL)

// ---------------- scratch (static device memory) ----------------------------
__device__ float g_y1[8*BCL];          // stage-1 outputs, [z][B][C][L]
__device__ float g_y2[8*BCL];          // depthwise outputs
__device__ float g_q [BCL];            // query features
__device__ float g_KV[2*Bb*C4L];       // [0]=K, [1]=V : [2][B][4C][L]
__device__ float g_x [BCL];            // attention output
__device__ float g_at[2*Bb*128*512];   // qk partial sums, 2 L-halves

__device__ __forceinline__ float gelu_exact(float x) {
    return 0.5f * x * (1.0f + erff(x * 0.70710678118654752f));
}

// ---------------------------------------------------------------------------
// Fused pointwise block: [optional in-LN+GELU] -> GEMM(128x128)+bias ->
// out-LN -> [optional GELU] -> [optional residual]
// Tile: 128 out-ch x 64 tokens, 256 threads, 8x4 accs per thread.
// flags: bit0 in LN+GELU, bit1 out GELU, bit2 residual
// offsets: ptr + (z>>2)*X2 + (z&3)*X1 + b*X0
// ---------------------------------------------------------------------------
__global__ __launch_bounds__(256) void pw_v2(
    const float* __restrict__ in0, const float* __restrict__ in1,
    const float* __restrict__ in2, const float* __restrict__ in3,
    int sel, long i2, long i1, long i0,
    const float* __restrict__ Wb, const float* __restrict__ biasb,
    const float* __restrict__ g1b, const float* __restrict__ b1b,
    const float* __restrict__ g2b, const float* __restrict__ b2b,
    int blk0,
    const float* __restrict__ res, long rbs,
    float* __restrict__ outb, long o2, long o1, long o0,
    int flags)
{
    __shared__ float xs[128 * 64];     // 32 KB input tile [c][t]
    __shared__ float ubuf[2176];       // union: wr[16*132] | red[2][64][17]

    const int tid  = threadIdx.x;
    const int ttok = tid & 15;         // token group (4 tokens)
    const int tout = tid >> 4;         // out-channel group (8 ch)
    const int b = blockIdx.y, z = blockIdx.z;
    const int l0 = blockIdx.x * 64;
    const int blk = blk0 + z;
    const int zm = z & 3, zh = z >> 2;

    const float* inbase = sel ? (zm == 0 ? in0 : zm == 1 ? in1 : zm == 2 ? in2 : in3) : in0;
    const float* inp  = inbase + (long)zh * i2 + (long)zm * i1 + (long)b * i0 + l0;
    const float* W    = Wb   + (long)blk * 128 * 128;
    const float* bias = biasb + blk * 128;
    const float* gi = g1b + blk * 128, *bi = b1b + blk * 128;
    const float* go = g2b + blk * 128, *bo = b2b + blk * 128;
    float* outp = outb + (long)zh * o2 + (long)zm * o1 + (long)b * o0 + l0;

    // load 128x64 input tile (float4, fully coalesced)
#pragma unroll
    for (int r = 0; r < 8; r++) {
        int idx = r * 256 + tid;            // float4 units
        int c = idx >> 4, t4 = idx & 15;
        *(float4*)&xs[c * 64 + t4 * 4] =
            *(const float4*)&inp[(long)c * Lsp + t4 * 4];
    }
    __syncthreads();

    float* red0 = ubuf;            // [64][17]
    float* red1 = ubuf + 1088;

    if (flags & 1) {               // input LayerNorm + GELU (per token, 128 ch)
        float s[4] = {0,0,0,0}, q[4] = {0,0,0,0};
#pragma unroll
        for (int i = 0; i < 8; i++) {
            int c = tout * 8 + i;
#pragma unroll
            for (int j = 0; j < 4; j++) {
                float x = xs[c * 64 + ttok * 4 + j];
                s[j] += x; q[j] += x * x;
            }
        }
#pragma unroll
        for (int j = 0; j < 4; j++) {
            red0[(ttok * 4 + j) * 17 + tout] = s[j];
            red1[(ttok * 4 + j) * 17 + tout] = q[j];
        }
        __syncthreads();
        float mean[4], rstd[4];
#pragma unroll
        for (int j = 0; j < 4; j++) {
            float S = 0.f, Q = 0.f;
#pragma unroll
            for (int p = 0; p < 16; p++) {
                S += red0[(ttok * 4 + j) * 17 + p];
                Q += red1[(ttok * 4 + j) * 17 + p];
            }
            mean[j] = S * (1.f / 128.f);
            rstd[j] = rsqrtf(Q * (1.f / 128.f) - mean[j] * mean[j] + 1e-6f);
        }
#pragma unroll
        for (int i = 0; i < 8; i++) {
            int c = tout * 8 + i;
            float gg = gi[c], bb = bi[c];
#pragma unroll
            for (int j = 0; j < 4; j++) {
                float x = xs[c * 64 + ttok * 4 + j];
                x = (x - mean[j]) * rstd[j] * gg + bb;
                xs[c * 64 + ttok * 4 + j] = gelu_exact(x);
            }
        }
    }

    // ---- GEMM: acc[8 out][4 tok] ----
    float acc[8][4];
#pragma unroll
    for (int i = 0; i < 8; i++) {
        float bv = bias[tout * 8 + i];
#pragma unroll
        for (int j = 0; j < 4; j++) acc[i][j] = bv;
    }

    float* wr = ubuf;                  // [16 k][132]
    for (int c0 = 0; c0 < 128; c0 += 16) {
        __syncthreads();
#pragma unroll
        for (int r = 0; r < 8; r++) {
            int idx = r * 256 + tid;
            int o = idx >> 4, cl = idx & 15;
            wr[cl * 132 + o] = W[o * 128 + c0 + cl];
        }
        __syncthreads();
#pragma unroll
        for (int cl = 0; cl < 16; cl++) {
            float4 xv = *(const float4*)&xs[(c0 + cl) * 64 + ttok * 4];
            float4 wa = *(const float4*)&wr[cl * 132 + tout * 8];
            float4 wb = *(const float4*)&wr[cl * 132 + tout * 8 + 4];
            float wv[8] = {wa.x, wa.y, wa.z, wa.w, wb.x, wb.y, wb.z, wb.w};
            float xvv[4] = {xv.x, xv.y, xv.z, xv.w};
#pragma unroll
            for (int i = 0; i < 8; i++)
#pragma unroll
                for (int j = 0; j < 4; j++)
                    acc[i][j] += wv[i] * xvv[j];
        }
    }

    // ---- output LayerNorm ----
    __syncthreads();
    {
        float s[4] = {0,0,0,0}, q[4] = {0,0,0,0};
#pragma unroll
        for (int i = 0; i < 8; i++)
#pragma unroll
            for (int j = 0; j < 4; j++) {
                s[j] += acc[i][j]; q[j] += acc[i][j] * acc[i][j];
            }
#pragma unroll
        for (int j = 0; j < 4; j++) {
            red0[(ttok * 4 + j) * 17 + tout] = s[j];
            red1[(ttok * 4 + j) * 17 + tout] = q[j];
        }
    }
    __syncthreads();
    float mean[4], rstd[4];
#pragma unroll
    for (int j = 0; j < 4; j++) {
        float S = 0.f, Q = 0.f;
#pragma unroll
        for (int p = 0; p < 16; p++) {
            S += red0[(ttok * 4 + j) * 17 + p];
            Q += red1[(ttok * 4 + j) * 17 + p];
        }
        mean[j] = S * (1.f / 128.f);
        rstd[j] = rsqrtf(Q * (1.f / 128.f) - mean[j] * mean[j] + 1e-6f);
    }

    const float* resp = (flags & 4) ? (res + (long)b * rbs + l0) : nullptr;
#pragma unroll
    for (int i = 0; i < 8; i++) {
        int o = tout * 8 + i;
        float gg = go[o], bb = bo[o];
        float4 vv;
        float* pv = &vv.x;
#pragma unroll
        for (int j = 0; j < 4; j++) {
            float v = (acc[i][j] - mean[j]) * rstd[j] * gg + bb;
            if (flags & 2) v = gelu_exact(v);
            pv[j] = v;
        }
        if (flags & 4) {
            float4 rr = *(const float4*)&resp[(long)o * Lsp + ttok * 4];
            vv.x += rr.x; vv.y += rr.y; vv.z += rr.z; vv.w += rr.w;
        }
        *(float4*)&outp[(long)o * Lsp + ttok * 4] = vv;
    }
}

// ---------------------------------------------------------------------------
// Depthwise 3x3x3 + bias. One block per (c, b, z-slab). Rolling 3-plane
// register window over a zero-padded smem volume.
// ---------------------------------------------------------------------------
__global__ __launch_bounds__(256) void dw_v2(
    const float* __restrict__ inb, float* __restrict__ outb,
    long iz, long ib,
    const float* __restrict__ w27b, const float* __restrict__ biasb, int blk0)
{
    __shared__ float sp[16 * 324];     // [z][y+1 of 18][x+1 of 18]
    const int tid = threadIdx.x;
    const int x = tid & 15, y = tid >> 4;
    const int c = blockIdx.x, b = blockIdx.y, z = blockIdx.z;
    const int blk = blk0 + z;

    const float* in = inb + (long)z * iz + (long)b * ib + (long)c * Lsp;
    float* out = outb + (long)z * iz + (long)b * ib + (long)c * Lsp;
    const float* wv = w27b + (long)blk * Cch * 27 + c * 27;
    const float bias = biasb[blk * Cch + c];

    for (int idx = tid; idx < 16 * 324; idx += 256) sp[idx] = 0.f;
    __syncthreads();
    for (int idx = tid; idx < 4096; idx += 256) {
        int zz = idx >> 8, rem = idx & 255;
        sp[zz * 324 + ((rem >> 4) + 1) * 18 + (rem & 15) + 1] = in[idx];
    }
    float w[27];
#pragma unroll
    for (int k = 0; k < 27; k++) w[k] = wv[k];
    __syncthreads();

    float p0[9], p1[9], p2[9];
#pragma unroll
    for (int k = 0; k < 9; k++) p0[k] = 0.f;
#pragma unroll
    for (int dy = 0; dy < 3; dy++)
#pragma unroll
        for (int dx = 0; dx < 3; dx++)
            p1[dy * 3 + dx] = sp[(y + dy) * 18 + (x + dx)];

#pragma unroll
    for (int zz = 0; zz < 16; zz++) {
        if (zz < 15) {
#pragma unroll
            for (int dy = 0; dy < 3; dy++)
#pragma unroll
                for (int dx = 0; dx < 3; dx++)
                    p2[dy * 3 + dx] = sp[(zz + 1) * 324 + (y + dy) * 18 + (x + dx)];
        } else {
#pragma unroll
            for (int k = 0; k < 9; k++) p2[k] = 0.f;
        }
        float a = bias;
#pragma unroll
        for (int k = 0; k < 9; k++) a += p0[k] * w[k];
#pragma unroll
        for (int k = 0; k < 9; k++) a += p1[k] * w[9 + k];
#pragma unroll
        for (int k = 0; k < 9; k++) a += p2[k] * w[18 + k];
        out[zz * 256 + tid] = a;
#pragma unroll
        for (int k = 0; k < 9; k++) { p0[k] = p1[k]; p1[k] = p2[k]; }
    }
}

// ---------------------------------------------------------------------------
// qk partial: at[half][b][c][k] = sum over half of L of q[c,l]*K[k,l]
// 64c x 64k tile, 4x4 accs. grid (8, 2, 16: b*2+half)
// ---------------------------------------------------------------------------
__global__ __launch_bounds__(256) void attn_qk2(
    const float* __restrict__ q, const float* __restrict__ K,
    float* __restrict__ at)
{
    __shared__ float qa[64 * 33];
    __shared__ float kb[64 * 33];
    const int tid = threadIdx.x;
    const int tk = tid & 15, tc = tid >> 4;
    const int k0 = blockIdx.x * 64, c0 = blockIdx.y * 64;
    const int b = blockIdx.z >> 1, half = blockIdx.z & 1;

    const float* qp = q + (long)b * CL + (long)c0 * Lsp;
    const float* Kp = K + (long)b * C4L + (long)k0 * Lsp;

    float acc[4][4];
#pragma unroll
    for (int i = 0; i < 4; i++)
#pragma unroll
        for (int j = 0; j < 4; j++) acc[i][j] = 0.f;

    const int lbeg = half * 2048;
    for (int l0 = lbeg; l0 < lbeg + 2048; l0 += 32) {
        __syncthreads();
#pragma unroll
        for (int r = 0; r < 8; r++) {
            int idx = r * 256 + tid;
            int row = idx >> 5, ll = idx & 31;
            qa[row * 33 + ll] = qp[(long)row * Lsp + l0 + ll];
            kb[row * 33 + ll] = Kp[(long)row * Lsp + l0 + ll];
        }
        __syncthreads();
#pragma unroll 4
        for (int ll = 0; ll < 32; ll++) {
            float qv[4], kv[4];
#pragma unroll
            for (int i = 0; i < 4; i++) qv[i] = qa[(tc * 4 + i) * 33 + ll];
#pragma unroll
            for (int j = 0; j < 4; j++) kv[j] = kb[(tk * 4 + j) * 33 + ll];
#pragma unroll
            for (int i = 0; i < 4; i++)
#pragma unroll
                for (int j = 0; j < 4; j++) acc[i][j] += qv[i] * kv[j];
        }
    }
    float* ap = at + (long)half * (Bb * 65536) + (long)b * 65536 + (long)c0 * 512 + k0;
#pragma unroll
    for (int i = 0; i < 4; i++)
#pragma unroll
        for (int j = 0; j < 4; j++)
            ap[(long)(tc * 4 + i) * 512 + tk * 4 + j] = acc[i][j];
}

// ---------------------------------------------------------------------------
// masked softmax over 512 keys; sums the two qk halves, applies 1/64 scale.
// result written to half-0 region.
// ---------------------------------------------------------------------------
__global__ __launch_bounds__(128) void softmax_mask(
    float* __restrict__ at, const int* __restrict__ mask)
{
    __shared__ float sm[128];
    const int row = blockIdx.x;            // b*128 + c
    const int b = row >> 7;
    const int t = threadIdx.x;
    float* p0 = at + (long)row * 512;
    const float* p1 = at + (long)Bb * 65536 + (long)row * 512;

    float v[4];
    float mx = -INFINITY;
#pragma unroll
    for (int j = 0; j < 4; j++) {
        bool on = mask[b * 4 + j] > 0;
        v[j] = on ? (p0[j * 128 + t] + p1[j * 128 + t]) * 0.015625f : -INFINITY;
        mx = fmaxf(mx, v[j]);
    }
    sm[t] = mx; __syncthreads();
    for (int s = 64; s > 0; s >>= 1) {
        if (t < s) sm[t] = fmaxf(sm[t], sm[t + s]);
        __syncthreads();
    }
    mx = sm[0]; __syncthreads();

    float sum = 0.f;
#pragma unroll
    for (int j = 0; j < 4; j++) {
        v[j] = (v[j] == -INFINITY) ? 0.f : expf(v[j] - mx);
        sum += v[j];
    }
    sm[t] = sum; __syncthreads();
    for (int s = 64; s > 0; s >>= 1) {
        if (t < s) sm[t] += sm[t + s];
        __syncthreads();
    }
    float inv = 1.f / sm[0];
#pragma unroll
    for (int j = 0; j < 4; j++) p0[j * 128 + t] = v[j] * inv;
}

// ---------------------------------------------------------------------------
// x[b,c,l] = sum_k attn[b,c,k] * V[b,k,l]. 64c x 64l tile, 4x4 accs.
// ---------------------------------------------------------------------------
__global__ __launch_bounds__(256) void attn_v2(
    const float* __restrict__ at, const float* __restrict__ V,
    float* __restrict__ xout)
{
    __shared__ float ac[64 * 33];
    __shared__ float vc[32 * 68];
    const int tid = threadIdx.x;
    const int tl = tid & 15, tc = tid >> 4;
    const int l0 = blockIdx.x * 64, c0 = blockIdx.y * 64;
    const int b = blockIdx.z;

    const float* ap = at + (long)b * 65536 + (long)c0 * 512;
    const float* Vp = V + (long)b * C4L;

    float acc[4][4];
#pragma unroll
    for (int i = 0; i < 4; i++)
#pragma unroll
        for (int j = 0; j < 4; j++) acc[i][j] = 0.f;

    for (int k0 = 0; k0 < 512; k0 += 32) {
        __syncthreads();
#pragma unroll
        for (int r = 0; r < 8; r++) {
            int idx = r * 256 + tid;            // ac: 64x32
            int row = idx >> 5, kk = idx & 31;
            ac[row * 33 + kk] = ap[(long)row * 512 + k0 + kk];
        }
#pragma unroll
        for (int r = 0; r < 2; r++) {
            int idx = r * 256 + tid;            // vc: 32 rows x 16 float4
            int row = idx >> 4, t4 = idx & 15;
            *(float4*)&vc[row * 68 + t4 * 4] =
                *(const float4*)&Vp[(long)(k0 + row) * Lsp + l0 + t4 * 4];
        }
        __syncthreads();
#pragma unroll 4
        for (int kk = 0; kk < 32; kk++) {
            float4 vv = *(const float4*)&vc[kk * 68 + tl * 4];
            float av[4];
#pragma unroll
            for (int i = 0; i < 4; i++) av[i] = ac[(tc * 4 + i) * 33 + kk];
            float* pv = &vv.x;
#pragma unroll
            for (int i = 0; i < 4; i++)
#pragma unroll
                for (int j = 0; j < 4; j++) acc[i][j] += av[i] * pv[j];
        }
    }
    float* op = xout + (long)b * CL + l0;
#pragma unroll
    for (int i = 0; i < 4; i++) {
        float4 vv = make_float4(acc[i][0], acc[i][1], acc[i][2], acc[i][3]);
        *(float4*)&op[(long)(c0 + tc * 4 + i) * Lsp + tl * 4] = vv;
    }
}

// ---------------------------------------------------------------------------
extern "C" void kernel_launch(void* const* d_in, const int* in_sizes, int n_in,
                              void* d_out, int out_size)
{
    const float* query = (const float*)d_in[0];
    const float* m0 = (const float*)d_in[1];
    const float* m1 = (const float*)d_in[2];
    const float* m2 = (const float*)d_in[3];
    const float* m3 = (const float*)d_in[4];
    const int*   mask  = (const int*)d_in[5];
    const float* pw1_w = (const float*)d_in[6];
    const float* pw1_b = (const float*)d_in[7];
    const float* ln1_g = (const float*)d_in[8];
    const float* ln1_b = (const float*)d_in[9];
    const float* dw_w  = (const float*)d_in[10];
    const float* dw_b  = (const float*)d_in[11];
    const float* ln2_g = (const float*)d_in[12];
    const float* ln2_b = (const float*)d_in[13];
    const float* pw2_w = (const float*)d_in[14];
    const float* pw2_b = (const float*)d_in[15];
    const float* ln3_g = (const float*)d_in[16];
    const float* ln3_b = (const float*)d_in[17];
    float* out = (float*)d_out;

    float *y1, *y2, *qb, *kv, *xb, *at;
    cudaGetSymbolAddress((void**)&y1, g_y1);
    cudaGetSymbolAddress((void**)&y2, g_y2);
    cudaGetSymbolAddress((void**)&qb, g_q);
    cudaGetSymbolAddress((void**)&kv, g_KV);
    cudaGetSymbolAddress((void**)&xb, g_x);
    cudaGetSymbolAddress((void**)&at, g_at);
    float* Kb = kv;
    float* Vb = kv + (long)Bb * C4L;

    const long S2 = 4L * BCL, S1 = BCL, S0 = CL;

    // ---- query block (blk 0) ----
    pw_v2<<<dim3(64, Bb, 1), 256>>>(query, query, query, query, 0, 0, 0, CL,
        pw1_w, pw1_b, ln1_g, ln1_b, ln1_g, ln1_b, 0,
        nullptr, 0, y1, S2, S1, S0, 2);
    dw_v2<<<dim3(Cch, Bb, 1), 256>>>(y1, y2, BCL, CL, dw_w, dw_b, 0);
    pw_v2<<<dim3(64, Bb, 1), 256>>>(y2, y2, y2, y2, 0, S2, S1, S0,
        pw2_w, pw2_b, ln2_g, ln2_b, ln3_g, ln3_b, 0,
        nullptr, 0, qb, 0, 0, CL, 1);

    // ---- K/V blocks (blk 1..8), batched over grid.z ----
    pw_v2<<<dim3(64, Bb, 8), 256>>>(m0, m1, m2, m3, 1, 0, 0, CL,
        pw1_w, pw1_b, ln1_g, ln1_b, ln1_g, ln1_b, 1,
        nullptr, 0, y1, S2, S1, S0, 2);
    dw_v2<<<dim3(Cch, Bb, 8), 256>>>(y1, y2, BCL, CL, dw_w, dw_b, 1);
    pw_v2<<<dim3(64, Bb, 8), 256>>>(y2, y2, y2, y2, 0, S2, S1, S0,
        pw2_w, pw2_b, ln2_g, ln2_b, ln3_g, ln3_b, 1,
        nullptr, 0, kv, (long)Bb * C4L, CL, C4L, 1);

    // ---- attention ----
    attn_qk2<<<dim3(8, 2, 16), 256>>>(qb, Kb, at);
    softmax_mask<<<Bb * 128, 128>>>(at, mask);
    attn_v2<<<dim3(64, 2, Bb), 256>>>(at, Vb, xb);

    // ---- out_project (blk 9) + residual ----
    pw_v2<<<dim3(64, Bb, 1), 256>>>(xb, xb, xb, xb, 0, 0, 0, CL,
        pw1_w, pw1_b, ln1_g, ln1_b, ln1_g, ln1_b, 9,
        nullptr, 0, y1, S2, S1, S0, 2);
    dw_v2<<<dim3(Cch, Bb, 1), 256>>>(y1, y2, BCL, CL, dw_w, dw_b, 9);
    pw_v2<<<dim3(64, Bb, 1), 256>>>(y2, y2, y2, y2, 0, S2, S1, S0,
        pw2_w, pw2_b, ln2_g, ln2_b, ln3_g, ln3_b, 9,
        query, CL, out, 0, 0, CL, 1 | 4);
}